// round 2
// baseline (speedup 1.0000x reference)
#include <cuda_runtime.h>
#include <math.h>
#include <stdint.h>

// Problem: B=64, T=1024, D=512, H=512
//   xw = x @ W[:512] + b              (65536x512x512 GEMM)
//   h_t = tanh(xw_t + h_{t-1} @ Wh)   scan over T=1024
//
// Phase 1: FFMA2 (packed f32x2) tiled GEMM -> g_xw scratch (unchanged from R1)
// Phase 2: 16 clusters x 8 CTAs. Cluster owns 4 batch rows; CTA owns 64
//          features with its 512x64 Wh slice in registers. Per step, each CTA
//          pushes its 4x64 h-chunk into every peer's smem slab (DSMEM) and
//          syncs with barrier.cluster — no gmem h round-trip, no global
//          software barrier.

__device__ float g_xw[64u * 1024u * 512u];      // 128 MB scratch: [b][t][h]

#define FMA2(d, a, b, c) \
    asm("fma.rn.f32x2 %0, %1, %2, %3;" : "=l"(d) : "l"(a), "l"(b), "l"(c))
#define PACK2(d, lo, hi) \
    asm("mov.b64 %0, {%1, %2};" : "=l"(d) : "f"(lo), "f"(hi))
#define UNPACK2(lo, hi, v) \
    asm("mov.b64 {%0, %1}, %2;" : "=f"(lo), "=f"(hi) : "l"(v))

// ---------------------------------------------------------------------------
// Phase 1: g_xw[m][n] = sum_k x[m][k] * W[k][n] + b[n],  m in [0,65536)
// ---------------------------------------------------------------------------
__global__ __launch_bounds__(256) void xw_gemm(const float* __restrict__ x,
                                               const float* __restrict__ W,
                                               const float* __restrict__ bias) {
    __shared__ __align__(16) float Ast[16][132];  // [k][m] transposed, padded
    __shared__ __align__(16) float Bs[16][128];   // [k][n]

    const int tid = threadIdx.x;
    const int bn = blockIdx.x & 3;
    const int bm = blockIdx.x >> 2;
    const int row0 = bm << 7;
    const int n0 = bn << 7;
    const int mt = tid >> 4;
    const int nt = tid & 15;

    unsigned long long acc[4][8];
#pragma unroll
    for (int p = 0; p < 4; p++)
#pragma unroll
        for (int j = 0; j < 8; j++) acc[p][j] = 0ULL;

    for (int kt = 0; kt < 512; kt += 16) {
#pragma unroll
        for (int it = 0; it < 2; it++) {
            int idx = tid + (it << 8);
            int m = idx >> 2;
            int kq = (idx & 3) << 2;
            float4 v = *(const float4*)(x + (size_t)(row0 + m) * 512 + kt + kq);
            Ast[kq + 0][m] = v.x;
            Ast[kq + 1][m] = v.y;
            Ast[kq + 2][m] = v.z;
            Ast[kq + 3][m] = v.w;
        }
#pragma unroll
        for (int it = 0; it < 2; it++) {
            int idx = tid + (it << 8);
            int k = idx >> 5;
            int nq = (idx & 31) << 2;
            *(float4*)(&Bs[k][nq]) =
                *(const float4*)(W + (size_t)(kt + k) * 512 + n0 + nq);
        }
        __syncthreads();
#pragma unroll
        for (int k = 0; k < 16; k++) {
            ulonglong2 aA = *(const ulonglong2*)(&Ast[k][4 * mt]);
            ulonglong2 aB = *(const ulonglong2*)(&Ast[k][64 + 4 * mt]);
            float4 b0 = *(const float4*)(&Bs[k][4 * nt]);
            float4 b1 = *(const float4*)(&Bs[k][64 + 4 * nt]);
            unsigned long long bb[8];
            PACK2(bb[0], b0.x, b0.x);
            PACK2(bb[1], b0.y, b0.y);
            PACK2(bb[2], b0.z, b0.z);
            PACK2(bb[3], b0.w, b0.w);
            PACK2(bb[4], b1.x, b1.x);
            PACK2(bb[5], b1.y, b1.y);
            PACK2(bb[6], b1.z, b1.z);
            PACK2(bb[7], b1.w, b1.w);
#pragma unroll
            for (int j = 0; j < 8; j++) {
                FMA2(acc[0][j], aA.x, bb[j], acc[0][j]);
                FMA2(acc[1][j], aA.y, bb[j], acc[1][j]);
                FMA2(acc[2][j], aB.x, bb[j], acc[2][j]);
                FMA2(acc[3][j], aB.y, bb[j], acc[3][j]);
            }
        }
        __syncthreads();
    }

    float bv[8];
#pragma unroll
    for (int j = 0; j < 4; j++) {
        bv[j] = bias[n0 + 4 * nt + j];
        bv[4 + j] = bias[n0 + 64 + 4 * nt + j];
    }
    float res[8][8];
#pragma unroll
    for (int p = 0; p < 4; p++)
#pragma unroll
        for (int j = 0; j < 8; j++) {
            float lo, hi;
            UNPACK2(lo, hi, acc[p][j]);
            res[2 * p][j] = lo + bv[j];
            res[2 * p + 1][j] = hi + bv[j];
        }
#pragma unroll
    for (int rI = 0; rI < 8; rI++) {
        int lrow = (rI < 4) ? (4 * mt + rI) : (64 + 4 * mt + (rI - 4));
        size_t base = (size_t)(row0 + lrow) * 512 + n0;
        float4 s0 = make_float4(res[rI][0], res[rI][1], res[rI][2], res[rI][3]);
        float4 s1 = make_float4(res[rI][4], res[rI][5], res[rI][6], res[rI][7]);
        *(float4*)(g_xw + base + 4 * nt) = s0;
        *(float4*)(g_xw + base + 64 + 4 * nt) = s1;
    }
}

// ---------------------------------------------------------------------------
// Phase 2: clustered scan.
//   grid = 128 CTAs, cluster = 8. cluster id = blockIdx.x/8 -> 4 batch rows.
//   rank = ctarank -> 64 feature cols. Wh slice (512k x 64c) in registers,
//   k split 4-ways across warps-pairs (128 k each).
//   h slab: smem hbuf[2][512][4]  ([buf][k][row]), written by ALL cluster
//   CTAs via st.shared::cluster, consumed directly by the mainloop.
// ---------------------------------------------------------------------------
__global__ __launch_bounds__(256, 1) __cluster_dims__(8, 1, 1)
void rnn_scan(const float* __restrict__ W, float* __restrict__ out) {
    __shared__ __align__(16) float hbuf[2][512][4];  // 16 KB
    __shared__ float red[4][4][68];                  // [kchunk][row][col]+pad

    const int tid = threadIdx.x;
    uint32_t rank;
    asm("mov.u32 %0, %%cluster_ctarank;" : "=r"(rank));
    const int r0 = (blockIdx.x >> 3) << 2;  // 4 batch rows per cluster
    const int c0 = ((int)rank) << 6;        // 64 cols per CTA

    const int c = tid & 63;   // col within tile
    const int ks = tid >> 6;  // k-chunk 0..3 (128 k each)

    // Wh slice into registers
    float wreg[128];
#pragma unroll
    for (int j = 0; j < 128; j++) {
        wreg[j] = W[(size_t)(512 + (ks << 7) + j) * 512 + c0 + c];
    }

    // peer slab base addresses (stable across the whole scan)
    uint32_t own;
    asm("{ .reg .u64 t; cvta.to.shared.u64 t, %1; cvt.u32.u64 %0, t; }"
        : "=r"(own)
        : "l"((void*)&hbuf[0][0][0]));
    uint32_t peer[8];
#pragma unroll
    for (int rk = 0; rk < 8; rk++) {
        asm("mapa.shared::cluster.u32 %0, %1, %2;"
            : "=r"(peer[rk])
            : "r"(own), "r"(rk));
    }

    const int rr = tid >> 6;  // epilogue row 0..3
    const int cc = tid & 63;  // epilogue col 0..63
    const uint32_t kfix = (uint32_t)((((c0 + cc) << 2) + rr) << 2);  // byte off

    for (int t = 0; t < 1024; t++) {
        // prefetch xw (independent of slab)
        float xwv =
            g_xw[((size_t)(r0 + rr) * 1024 + (size_t)t) * 512 + c0 + cc];

        unsigned long long acc01 = 0ULL, acc23 = 0ULL;
        if (t > 0) {
            const float* hb = &hbuf[t & 1][0][0];
            const int kb = ks << 7;
#pragma unroll
            for (int j = 0; j < 128; j++) {
                ulonglong2 h4 = *(const ulonglong2*)(hb + ((kb + j) << 2));
                unsigned long long w2;
                PACK2(w2, wreg[j], wreg[j]);
                FMA2(acc01, h4.x, w2, acc01);  // rows 0,1
                FMA2(acc23, h4.y, w2, acc23);  // rows 2,3
            }
        }
        // cross-k-chunk reduction via smem
        float p0, p1;
        UNPACK2(p0, p1, acc01);
        red[ks][0][c] = p0;
        red[ks][1][c] = p1;
        UNPACK2(p0, p1, acc23);
        red[ks][2][c] = p0;
        red[ks][3][c] = p1;
        __syncthreads();

        float s = xwv + red[0][rr][cc] + red[1][rr][cc] + red[2][rr][cc] +
                  red[3][rr][cc];
        float v = tanhf(s);

        out[((size_t)(r0 + rr) * 1024 + (size_t)t) * 512 + c0 + cc] = v;

        if (t < 1023) {
            // push h into every cluster CTA's next-buffer slab
            uint32_t off = kfix + (uint32_t)(((t + 1) & 1) << 13);
#pragma unroll
            for (int rk = 0; rk < 8; rk++) {
                asm volatile("st.shared::cluster.f32 [%0], %1;" ::"r"(
                                 peer[rk] + off),
                             "f"(v)
                             : "memory");
            }
            // hardware cluster barrier: orders the DSMEM pushes, and doubles
            // as the intra-CTA barrier protecting red[] reuse next step
            asm volatile("barrier.cluster.arrive.aligned;" ::: "memory");
            asm volatile("barrier.cluster.wait.aligned;" ::: "memory");
        }
    }
}

// ---------------------------------------------------------------------------
extern "C" void kernel_launch(void* const* d_in, const int* in_sizes, int n_in,
                              void* d_out, int out_size) {
    const float* x = (const float*)d_in[0];  // (64, 1024, 512) f32
    const float* W = (const float*)d_in[1];  // (1024, 512) f32
    const float* b = (const float*)d_in[2];  // (512,) f32
    float* out = (float*)d_out;              // (64, 1024, 512) f32

    xw_gemm<<<2048, 256>>>(x, W, b);
    rnn_scan<<<128, 256>>>(W, out);
}

// round 3
// speedup vs baseline: 1.9084x; 1.9084x over previous
#include <cuda_runtime.h>
#include <math.h>
#include <stdint.h>

// Problem: B=64, T=1024, D=512, H=512
//   xw = x @ W[:512] + b              (65536x512x512 GEMM)
//   h_t = tanh(xw_t + h_{t-1} @ Wh)   scan over T=1024
//
// Phase 1: FFMA2 (packed f32x2) tiled GEMM -> g_xw scratch
// Phase 2: 128 persistent CTAs = 8 row-groups x 16 col-splits.
//          Sync scope is ONLY the 16 CTAs of a row group (batch rows are
//          independent scans). Per-group monotonic counter in gmem:
//          producers red.release.gpu.add, consumer spins ld.acquire.gpu.
//          h ping-pongs through L2 in k-major layout (coalesced refill).

__device__ float g_xw[64u * 1024u * 512u];   // 128 MB scratch: [b][t][h]
__device__ float g_h[2][8][4096];            // [buf][group][k*8+row]
__device__ unsigned int g_cnt[8 * 64];       // per-group counters, 256B apart

#define FMA2(d, a, b, c) \
    asm("fma.rn.f32x2 %0, %1, %2, %3;" : "=l"(d) : "l"(a), "l"(b), "l"(c))
#define PACK2(d, lo, hi) \
    asm("mov.b64 %0, {%1, %2};" : "=l"(d) : "f"(lo), "f"(hi))
#define UNPACK2(lo, hi, v) \
    asm("mov.b64 {%0, %1}, %2;" : "=f"(lo), "=f"(hi) : "l"(v))

// ---------------------------------------------------------------------------
// Phase 1: g_xw[m][n] = sum_k x[m][k] * W[k][n] + b[n]
// ---------------------------------------------------------------------------
__global__ __launch_bounds__(256) void xw_gemm(const float* __restrict__ x,
                                               const float* __restrict__ W,
                                               const float* __restrict__ bias) {
    __shared__ __align__(16) float Ast[16][132];
    __shared__ __align__(16) float Bs[16][128];

    const int tid = threadIdx.x;
    const int bn = blockIdx.x & 3;
    const int bm = blockIdx.x >> 2;
    const int row0 = bm << 7;
    const int n0 = bn << 7;
    const int mt = tid >> 4;
    const int nt = tid & 15;

    unsigned long long acc[4][8];
#pragma unroll
    for (int p = 0; p < 4; p++)
#pragma unroll
        for (int j = 0; j < 8; j++) acc[p][j] = 0ULL;

    for (int kt = 0; kt < 512; kt += 16) {
#pragma unroll
        for (int it = 0; it < 2; it++) {
            int idx = tid + (it << 8);
            int m = idx >> 2;
            int kq = (idx & 3) << 2;
            float4 v = *(const float4*)(x + (size_t)(row0 + m) * 512 + kt + kq);
            Ast[kq + 0][m] = v.x;
            Ast[kq + 1][m] = v.y;
            Ast[kq + 2][m] = v.z;
            Ast[kq + 3][m] = v.w;
        }
#pragma unroll
        for (int it = 0; it < 2; it++) {
            int idx = tid + (it << 8);
            int k = idx >> 5;
            int nq = (idx & 31) << 2;
            *(float4*)(&Bs[k][nq]) =
                *(const float4*)(W + (size_t)(kt + k) * 512 + n0 + nq);
        }
        __syncthreads();
#pragma unroll
        for (int k = 0; k < 16; k++) {
            ulonglong2 aA = *(const ulonglong2*)(&Ast[k][4 * mt]);
            ulonglong2 aB = *(const ulonglong2*)(&Ast[k][64 + 4 * mt]);
            float4 b0 = *(const float4*)(&Bs[k][4 * nt]);
            float4 b1 = *(const float4*)(&Bs[k][64 + 4 * nt]);
            unsigned long long bb[8];
            PACK2(bb[0], b0.x, b0.x);
            PACK2(bb[1], b0.y, b0.y);
            PACK2(bb[2], b0.z, b0.z);
            PACK2(bb[3], b0.w, b0.w);
            PACK2(bb[4], b1.x, b1.x);
            PACK2(bb[5], b1.y, b1.y);
            PACK2(bb[6], b1.z, b1.z);
            PACK2(bb[7], b1.w, b1.w);
#pragma unroll
            for (int j = 0; j < 8; j++) {
                FMA2(acc[0][j], aA.x, bb[j], acc[0][j]);
                FMA2(acc[1][j], aA.y, bb[j], acc[1][j]);
                FMA2(acc[2][j], aB.x, bb[j], acc[2][j]);
                FMA2(acc[3][j], aB.y, bb[j], acc[3][j]);
            }
        }
        __syncthreads();
    }

    float bv[8];
#pragma unroll
    for (int j = 0; j < 4; j++) {
        bv[j] = bias[n0 + 4 * nt + j];
        bv[4 + j] = bias[n0 + 64 + 4 * nt + j];
    }
    float res[8][8];
#pragma unroll
    for (int p = 0; p < 4; p++)
#pragma unroll
        for (int j = 0; j < 8; j++) {
            float lo, hi;
            UNPACK2(lo, hi, acc[p][j]);
            res[2 * p][j] = lo + bv[j];
            res[2 * p + 1][j] = hi + bv[j];
        }
#pragma unroll
    for (int rI = 0; rI < 8; rI++) {
        int lrow = (rI < 4) ? (4 * mt + rI) : (64 + 4 * mt + (rI - 4));
        size_t base = (size_t)(row0 + lrow) * 512 + n0;
        float4 s0 = make_float4(res[rI][0], res[rI][1], res[rI][2], res[rI][3]);
        float4 s1 = make_float4(res[rI][4], res[rI][5], res[rI][6], res[rI][7]);
        *(float4*)(g_xw + base + 4 * nt) = s0;
        *(float4*)(g_xw + base + 64 + 4 * nt) = s1;
    }
}

// ---------------------------------------------------------------------------
__global__ void init_cnt() {
    if (threadIdx.x < 8 * 64) g_cnt[threadIdx.x] = 0u;
}

// ---------------------------------------------------------------------------
// Phase 2: per-group-synced scan.
//   CTA (g, s): rows r0..r0+7 (g = bid>>4), cols c0..c0+31 (s = bid&15).
//   Wh slice 512x32 in registers (64 floats/thread), k split 8-ways.
//   Step: [poll group cnt >= 16t] -> slab refill (16KB, float4) ->
//         64-iter FMA2 mainloop -> smem k-reduce -> tanh -> out +
//         h chunk store -> red.release.gpu.add(cnt).
// ---------------------------------------------------------------------------
__global__ __launch_bounds__(256, 1) void rnn_scan(const float* __restrict__ W,
                                                   float* __restrict__ out) {
    __shared__ __align__(16) float hst[4096];  // [k][row0..7], 16 KB
    __shared__ float red[8][8][33];            // [kchunk][row][col]

    const int bid = blockIdx.x;
    const int g = bid >> 4;            // row group 0..7
    const int r0 = g << 3;             // 8 batch rows
    const int c0 = (bid & 15) << 5;    // 32 feature cols
    const int tid = threadIdx.x;
    const int c = tid & 31;            // col within tile
    const int ks = tid >> 5;           // k-chunk 0..7 (64 k each)

    unsigned int* const cnt = &g_cnt[g * 64];

    // Wh slice into registers: wreg[j] = W[512 + ks*64 + j][c0 + c]
    float wreg[64];
#pragma unroll
    for (int j = 0; j < 64; j++) {
        wreg[j] = W[(size_t)(512 + (ks << 6) + j) * 512 + c0 + c];
    }

    const int rr = tid >> 5;  // epilogue row 0..7
    const int cc = tid & 31;  // epilogue col 0..31

    for (int t = 0; t < 1024; t++) {
        // xw prefetch (independent of h) — overlaps the poll + refill
        float xwv =
            g_xw[((size_t)(r0 + rr) * 1024 + (size_t)t) * 512 + c0 + cc];

        unsigned long long acc0 = 0ULL, acc1 = 0ULL, acc2 = 0ULL, acc3 = 0ULL;
        if (t > 0) {
            // wait for all 16 CTAs of this group to have published h(t)
            if (tid == 0) {
                const unsigned int tgt = (unsigned int)(t << 4);
                unsigned int cur;
                do {
                    asm volatile("ld.acquire.gpu.u32 %0, [%1];"
                                 : "=r"(cur)
                                 : "l"(cnt)
                                 : "memory");
                } while (cur < tgt);
            }
            __syncthreads();

            // slab refill: 4096 floats, 4 float4 per thread, coalesced
            const float* hb = g_h[t & 1][g];
#pragma unroll
            for (int i = 0; i < 4; i++) {
                *(float4*)(&hst[tid * 16 + i * 4]) =
                    *(const float4*)(hb + tid * 16 + i * 4);
            }
            __syncthreads();

#pragma unroll
            for (int j = 0; j < 64; j++) {
                int k = (ks << 6) + j;
                ulonglong2 hA = *(const ulonglong2*)(&hst[k * 8]);
                ulonglong2 hB = *(const ulonglong2*)(&hst[k * 8 + 4]);
                unsigned long long w2;
                PACK2(w2, wreg[j], wreg[j]);
                FMA2(acc0, hA.x, w2, acc0);  // rows 0,1
                FMA2(acc1, hA.y, w2, acc1);  // rows 2,3
                FMA2(acc2, hB.x, w2, acc2);  // rows 4,5
                FMA2(acc3, hB.y, w2, acc3);  // rows 6,7
            }
        }
        // cross-k-chunk reduction
        float p0, p1;
        UNPACK2(p0, p1, acc0); red[ks][0][c] = p0; red[ks][1][c] = p1;
        UNPACK2(p0, p1, acc1); red[ks][2][c] = p0; red[ks][3][c] = p1;
        UNPACK2(p0, p1, acc2); red[ks][4][c] = p0; red[ks][5][c] = p1;
        UNPACK2(p0, p1, acc3); red[ks][6][c] = p0; red[ks][7][c] = p1;
        __syncthreads();

        float s = xwv;
#pragma unroll
        for (int q = 0; q < 8; q++) s += red[q][rr][cc];
        float v = tanhf(s);

        out[((size_t)(r0 + rr) * 1024 + (size_t)t) * 512 + c0 + cc] = v;

        if (t < 1023) {
            // publish h(t+1) chunk: k-major so consumer refill is coalesced
            g_h[(t + 1) & 1][g][((c0 + cc) << 3) + rr] = v;
            __syncthreads();  // all stores issued (also protects red[] reuse)
            if (tid == 0) {
                // release: cumulative over bar.sync -> orders all CTA stores
                asm volatile("red.release.gpu.global.add.u32 [%0], %1;" ::"l"(
                                 cnt),
                             "r"(1u)
                             : "memory");
            }
        }
    }
}

// ---------------------------------------------------------------------------
extern "C" void kernel_launch(void* const* d_in, const int* in_sizes, int n_in,
                              void* d_out, int out_size) {
    const float* x = (const float*)d_in[0];  // (64, 1024, 512) f32
    const float* W = (const float*)d_in[1];  // (1024, 512) f32
    const float* b = (const float*)d_in[2];  // (512,) f32
    float* out = (float*)d_out;              // (64, 1024, 512) f32

    xw_gemm<<<2048, 256>>>(x, W, b);
    init_cnt<<<1, 512>>>();
    rnn_scan<<<128, 256>>>(W, out);
}

// round 4
// speedup vs baseline: 2.0646x; 1.0818x over previous
#include <cuda_runtime.h>
#include <math.h>
#include <stdint.h>

// Problem: B=64, T=1024, D=512, H=512
//   xw = x @ W[:512] + b              (65536x512x512 GEMM)
//   h_t = tanh(xw_t + h_{t-1} @ Wh)   scan over T=1024
//
// Phase 1: FFMA2 (packed f32x2) tiled GEMM -> g_xw scratch
// Phase 2: 128 persistent CTAs = 8 row-groups x 16 col-splits.
//          Per-producer release flags (no shared atomic), per-WARP polling
//          (each warp needs only 2 producers' data), per-warp 2KB slice
//          refill without CTA barrier, pre-packed f32x2 weights.

__device__ float g_xw[64u * 1024u * 512u];   // 128 MB scratch: [b][t][h]
__device__ float g_h[2][8][4096];            // [buf][group][feature*8+row]
__device__ unsigned int g_flag[8 * 16 * 32]; // [group][producer] 128B apart

#define FMA2(d, a, b, c) \
    asm("fma.rn.f32x2 %0, %1, %2, %3;" : "=l"(d) : "l"(a), "l"(b), "l"(c))
#define PACK2(d, lo, hi) \
    asm("mov.b64 %0, {%1, %2};" : "=l"(d) : "f"(lo), "f"(hi))
#define UNPACK2(lo, hi, v) \
    asm("mov.b64 {%0, %1}, %2;" : "=f"(lo), "=f"(hi) : "l"(v))

// ---------------------------------------------------------------------------
// Phase 1: g_xw[m][n] = sum_k x[m][k] * W[k][n] + b[n]
// ---------------------------------------------------------------------------
__global__ __launch_bounds__(256) void xw_gemm(const float* __restrict__ x,
                                               const float* __restrict__ W,
                                               const float* __restrict__ bias) {
    __shared__ __align__(16) float Ast[16][132];
    __shared__ __align__(16) float Bs[16][128];

    const int tid = threadIdx.x;
    const int bn = blockIdx.x & 3;
    const int bm = blockIdx.x >> 2;
    const int row0 = bm << 7;
    const int n0 = bn << 7;
    const int mt = tid >> 4;
    const int nt = tid & 15;

    unsigned long long acc[4][8];
#pragma unroll
    for (int p = 0; p < 4; p++)
#pragma unroll
        for (int j = 0; j < 8; j++) acc[p][j] = 0ULL;

    for (int kt = 0; kt < 512; kt += 16) {
#pragma unroll
        for (int it = 0; it < 2; it++) {
            int idx = tid + (it << 8);
            int m = idx >> 2;
            int kq = (idx & 3) << 2;
            float4 v = *(const float4*)(x + (size_t)(row0 + m) * 512 + kt + kq);
            Ast[kq + 0][m] = v.x;
            Ast[kq + 1][m] = v.y;
            Ast[kq + 2][m] = v.z;
            Ast[kq + 3][m] = v.w;
        }
#pragma unroll
        for (int it = 0; it < 2; it++) {
            int idx = tid + (it << 8);
            int k = idx >> 5;
            int nq = (idx & 31) << 2;
            *(float4*)(&Bs[k][nq]) =
                *(const float4*)(W + (size_t)(kt + k) * 512 + n0 + nq);
        }
        __syncthreads();
#pragma unroll
        for (int k = 0; k < 16; k++) {
            ulonglong2 aA = *(const ulonglong2*)(&Ast[k][4 * mt]);
            ulonglong2 aB = *(const ulonglong2*)(&Ast[k][64 + 4 * mt]);
            float4 b0 = *(const float4*)(&Bs[k][4 * nt]);
            float4 b1 = *(const float4*)(&Bs[k][64 + 4 * nt]);
            unsigned long long bb[8];
            PACK2(bb[0], b0.x, b0.x);
            PACK2(bb[1], b0.y, b0.y);
            PACK2(bb[2], b0.z, b0.z);
            PACK2(bb[3], b0.w, b0.w);
            PACK2(bb[4], b1.x, b1.x);
            PACK2(bb[5], b1.y, b1.y);
            PACK2(bb[6], b1.z, b1.z);
            PACK2(bb[7], b1.w, b1.w);
#pragma unroll
            for (int j = 0; j < 8; j++) {
                FMA2(acc[0][j], aA.x, bb[j], acc[0][j]);
                FMA2(acc[1][j], aA.y, bb[j], acc[1][j]);
                FMA2(acc[2][j], aB.x, bb[j], acc[2][j]);
                FMA2(acc[3][j], aB.y, bb[j], acc[3][j]);
            }
        }
        __syncthreads();
    }

    float bv[8];
#pragma unroll
    for (int j = 0; j < 4; j++) {
        bv[j] = bias[n0 + 4 * nt + j];
        bv[4 + j] = bias[n0 + 64 + 4 * nt + j];
    }
    float res[8][8];
#pragma unroll
    for (int p = 0; p < 4; p++)
#pragma unroll
        for (int j = 0; j < 8; j++) {
            float lo, hi;
            UNPACK2(lo, hi, acc[p][j]);
            res[2 * p][j] = lo + bv[j];
            res[2 * p + 1][j] = hi + bv[j];
        }
#pragma unroll
    for (int rI = 0; rI < 8; rI++) {
        int lrow = (rI < 4) ? (4 * mt + rI) : (64 + 4 * mt + (rI - 4));
        size_t base = (size_t)(row0 + lrow) * 512 + n0;
        float4 s0 = make_float4(res[rI][0], res[rI][1], res[rI][2], res[rI][3]);
        float4 s1 = make_float4(res[rI][4], res[rI][5], res[rI][6], res[rI][7]);
        *(float4*)(g_xw + base + 4 * nt) = s0;
        *(float4*)(g_xw + base + 64 + 4 * nt) = s1;
    }
}

// ---------------------------------------------------------------------------
__global__ void init_flags() {
    int i = blockIdx.x * blockDim.x + threadIdx.x;
    if (i < 8 * 16 * 32) g_flag[i] = 0u;
}

// ---------------------------------------------------------------------------
// Phase 2: per-warp-synced scan.
//   CTA (g, s): rows r0..r0+7 (g = bid>>4), cols c0..c0+31 (s = bid&15).
//   Warp ks consumes features [64ks, 64ks+64) = producers 2ks, 2ks+1 only.
//   Step: [warp polls its 2 flags] -> warp refills its 2KB slice ->
//         64-iter FMA2 mainloop -> smem k-reduce (bar) -> tanh ->
//         out + h stores (bar) -> tid0 st.release flag = t+1.
// ---------------------------------------------------------------------------
__global__ __launch_bounds__(256, 1) void rnn_scan(const float* __restrict__ W,
                                                   float* __restrict__ out) {
    __shared__ __align__(16) float hst[4096];  // [feature][row0..7], 16 KB
    __shared__ float red[8][8][33];            // [kchunk][row][col]

    const int bid = blockIdx.x;
    const int g = bid >> 4;          // row group 0..7
    const int r0 = g << 3;           // 8 batch rows
    const int s = bid & 15;          // col split 0..15
    const int c0 = s << 5;           // 32 feature cols
    const int tid = threadIdx.x;
    const int c = tid & 31;          // col within tile (== lane)
    const int ks = tid >> 5;         // warp id == k-chunk 0..7 (64 k each)
    const int lane = tid & 31;

    // my producer flag: lanes 0-15 watch producer 2ks, lanes 16-31 watch 2ks+1
    const unsigned int* myflag =
        &g_flag[((g << 4) + (ks << 1) + (lane >> 4)) << 5];
    // flag I publish
    unsigned int* pubflag = &g_flag[((g << 4) + s) << 5];

    // Wh slice pre-packed as f32x2 {w,w}: wpk[j] for k = ks*64+j, col c0+c
    unsigned long long wpk[64];
#pragma unroll
    for (int j = 0; j < 64; j++) {
        float w = W[(size_t)(512 + (ks << 6) + j) * 512 + c0 + c];
        PACK2(wpk[j], w, w);
    }

    const int rr = ks;        // epilogue row == warp id
    const int cc = c;         // epilogue col == lane

    float* const hslice = &hst[ks << 9];  // this warp's 512-float slice

    for (int t = 0; t < 1024; t++) {
        // xw prefetch (independent of h) — overlaps poll + refill + mainloop
        float xwv =
            g_xw[((size_t)(r0 + rr) * 1024 + (size_t)t) * 512 + c0 + cc];

        unsigned long long acc0 = 0ULL, acc1 = 0ULL, acc2 = 0ULL, acc3 = 0ULL;
        if (t > 0) {
            // per-warp poll: wait until both producers published step t
            const unsigned int tgt = (unsigned int)t;
            unsigned int fv;
            do {
                asm volatile("ld.acquire.gpu.u32 %0, [%1];"
                             : "=r"(fv)
                             : "l"(myflag)
                             : "memory");
            } while (__any_sync(0xffffffffu, fv < tgt));

            // per-warp slice refill: 512 floats (lanes 0-15 from producer 2ks,
            // lanes 16-31 from producer 2ks+1 — matches each lane's acquire)
            const float4* src =
                (const float4*)&g_h[t & 1][g][(unsigned)(ks << 9)];
            float4* dst = (float4*)hslice;
#pragma unroll
            for (int i = 0; i < 4; i++) {
                dst[(lane << 2) + i] = src[(lane << 2) + i];
            }
            __syncwarp();

#pragma unroll
            for (int j = 0; j < 64; j++) {
                ulonglong2 hA = *(const ulonglong2*)(hslice + (j << 3));
                ulonglong2 hB = *(const ulonglong2*)(hslice + (j << 3) + 4);
                FMA2(acc0, hA.x, wpk[j], acc0);  // rows 0,1
                FMA2(acc1, hA.y, wpk[j], acc1);  // rows 2,3
                FMA2(acc2, hB.x, wpk[j], acc2);  // rows 4,5
                FMA2(acc3, hB.y, wpk[j], acc3);  // rows 6,7
            }
        }
        // cross-k-chunk reduction
        float p0, p1;
        UNPACK2(p0, p1, acc0); red[ks][0][c] = p0; red[ks][1][c] = p1;
        UNPACK2(p0, p1, acc1); red[ks][2][c] = p0; red[ks][3][c] = p1;
        UNPACK2(p0, p1, acc2); red[ks][4][c] = p0; red[ks][5][c] = p1;
        UNPACK2(p0, p1, acc3); red[ks][6][c] = p0; red[ks][7][c] = p1;
        __syncthreads();

        float sum = xwv;
#pragma unroll
        for (int q = 0; q < 8; q++) sum += red[q][rr][cc];
        float v = tanhf(sum);

        out[((size_t)(r0 + rr) * 1024 + (size_t)t) * 512 + c0 + cc] = v;

        if (t < 1023) {
            // publish h(t+1) chunk (k-major so consumer refill is coalesced)
            g_h[(t + 1) & 1][g][((c0 + cc) << 3) + rr] = v;
            __syncthreads();  // all 256 h-stores ordered before the release;
                              // also protects red[] reuse next iteration
            if (tid == 0) {
                asm volatile("st.release.gpu.global.u32 [%0], %1;" ::"l"(
                                 pubflag),
                             "r"((unsigned int)(t + 1))
                             : "memory");
            }
        }
    }
}

// ---------------------------------------------------------------------------
extern "C" void kernel_launch(void* const* d_in, const int* in_sizes, int n_in,
                              void* d_out, int out_size) {
    const float* x = (const float*)d_in[0];  // (64, 1024, 512) f32
    const float* W = (const float*)d_in[1];  // (1024, 512) f32
    const float* b = (const float*)d_in[2];  // (512,) f32
    float* out = (float*)d_out;              // (64, 1024, 512) f32

    xw_gemm<<<2048, 256>>>(x, W, b);
    init_flags<<<16, 256>>>();
    rnn_scan<<<128, 256>>>(W, out);
}